// round 16
// baseline (speedup 1.0000x reference)
#include <cuda_runtime.h>
#include <cuda_fp16.h>
#include <math.h>
#include <stdint.h>

// Problem constants
#define NS 256
#define LR 384
#define DM 256
#define DP 128
#define NH 8
#define DHH 32
#define HDM 256
#define NL (NS*LR)      // 98304
#define LL (LR*LR)      // 147456
#define SCALE_DH 0.17677669529663687f

// ---------------- device scratch ----------------
__device__ float g_msan[LR*DM];           // only n=0 rows needed (swq)
__device__ float g_swq[LR*HDM];
__device__ float g_lbias[LR*NH];
__device__ __half g_gate[NL*HDM];
__device__ float g_logit[LR*NH*NS];
__device__ float g_attn[NH*LL];           // pair bias, then += qk logits (split-K atomics)

// packed fp16 operands
__device__ __half a_pk[(size_t)NL*256];            // [r][256]: msan (proj) / gated-out (out)
__device__ __half b_pk[1280*256];                  // proj weights^T, [n][256]
__device__ __half wo_pk[DM*256];                   // wo^T, [n][256]
__device__ __half q_pk[(size_t)NH*LR*8192];        // [h*384+l][n*32+d], raw then weighted
__device__ __half k_pk[(size_t)NH*LR*8192];        // [h*384+l][n*32+d]
__device__ __half vt_pk[(size_t)NH*NS*DHH*LR];     // [h*8192+(s*32+d)][l]
__device__ __half p_pk[(size_t)NH*LR*384];         // [h*384+q][k]

// ---------------- helpers ----------------
__device__ __forceinline__ float warpRed(float v){
    #pragma unroll
    for(int o=16;o>0;o>>=1) v += __shfl_xor_sync(0xffffffffu, v, o);
    return v;
}
__device__ __forceinline__ float warpMax(float v){
    #pragma unroll
    for(int o=16;o>0;o>>=1) v = fmaxf(v, __shfl_xor_sync(0xffffffffu, v, o));
    return v;
}
__device__ __forceinline__ uint32_t s2u(const void* p){
    uint32_t a; asm("{ .reg .u64 t; cvta.to.shared.u64 t, %1; cvt.u32.u64 %0, t; }" : "=r"(a) : "l"(p));
    return a;
}

// ---------------- 1. LayerNorm of msa + pack A (warp per row) ----------------
__global__ void ln_msa_kernel(const float* __restrict__ x,
                              const float* __restrict__ gg,
                              const float* __restrict__ bb){
    int warp = threadIdx.x>>5, lane = threadIdx.x&31;
    int row = blockIdx.x*8 + warp;
    const float4* xr = (const float4*)(x + (size_t)row*DM);
    float4 v0 = xr[lane], v1 = xr[lane+32];
    float sum = v0.x+v0.y+v0.z+v0.w + v1.x+v1.y+v1.z+v1.w;
    float sq  = v0.x*v0.x+v0.y*v0.y+v0.z*v0.z+v0.w*v0.w
              + v1.x*v1.x+v1.y*v1.y+v1.z*v1.z+v1.w*v1.w;
    sum = warpRed(sum); sq = warpRed(sq);
    float mean = sum*(1.f/DM);
    float var  = sq*(1.f/DM) - mean*mean;
    float inv  = rsqrtf(var + 1e-5f);
    float4 g0 = ((const float4*)gg)[lane], g1 = ((const float4*)gg)[lane+32];
    float4 b0 = ((const float4*)bb)[lane], b1 = ((const float4*)bb)[lane+32];
    float y0 = (v0.x-mean)*inv*g0.x + b0.x;
    float y1 = (v0.y-mean)*inv*g0.y + b0.y;
    float y2 = (v0.z-mean)*inv*g0.z + b0.z;
    float y3 = (v0.w-mean)*inv*g0.w + b0.w;
    float y4 = (v1.x-mean)*inv*g1.x + b1.x;
    float y5 = (v1.y-mean)*inv*g1.y + b1.y;
    float y6 = (v1.z-mean)*inv*g1.z + b1.z;
    float y7 = (v1.w-mean)*inv*g1.w + b1.w;
    if(row < LR){
        float4* mr = (float4*)(g_msan + row*DM);
        mr[lane]    = make_float4(y0,y1,y2,y3);
        mr[lane+32] = make_float4(y4,y5,y6,y7);
    }
    __half2* ap = (__half2*)(a_pk + (size_t)row*256);
    ap[lane*2]      = __floats2half2_rn(y0,y1);
    ap[lane*2+1]    = __floats2half2_rn(y2,y3);
    ap[64+lane*2]   = __floats2half2_rn(y4,y5);
    ap[64+lane*2+1] = __floats2half2_rn(y6,y7);
}

// ---------------- 2. pack weights (transposed, single fp16) ----------------
__global__ void pack_w_kernel(const float* __restrict__ wq, const float* __restrict__ wk,
                              const float* __restrict__ wv, const float* __restrict__ wg,
                              const float* __restrict__ wsk, const float* __restrict__ wo){
    int n = blockIdx.x, k = threadIdx.x;
    if(n < 1280){
        int mat = n >> 8, nl = n & 255;
        const float* W = (mat==0)?wq:(mat==1)?wk:(mat==2)?wv:(mat==3)?wg:wsk;
        b_pk[n*256 + k] = __float2half(W[k*HDM + nl]);
    } else {
        int nl = n - 1280;
        wo_pk[nl*256 + k] = __float2half(wo[k*DM + nl]);
    }
}

// ---------------- 3. swq (+ fused lbias) ----------------
__global__ void swq_kernel(const float* __restrict__ W, const float* __restrict__ bqb,
                           const float* __restrict__ skb){
    __shared__ float t[DM];
    int l = blockIdx.x, tid = threadIdx.x, lane = tid&31;
    t[tid] = g_msan[l*DM + tid];
    __syncthreads();
    float acc = 0.f;
    #pragma unroll 8
    for(int k=0;k<DM;k++) acc += t[k]*W[k*HDM + tid];
    float val = (acc + bqb[tid]) * SCALE_DH;
    g_swq[l*HDM + tid] = val;
    float pv = val * skb[tid];
    pv = warpRed(pv);
    if(lane==0) g_lbias[l*NH + (tid>>5)] = pv;
}

// ---------------- shared GEMM pieces ----------------
#define STG_BYTES 36864
#define B_OFF_BYTES 18432
#define NSTAGE 3
#define GSMEM_BYTES (NSTAGE*STG_BYTES)  // 110592

// ---------------- proj GEMM: BM=128, BN=256, 8 warps x (64x64), 3-stage ----------------
#define P_STG_BYTES 55296               // (128 A + 256 B rows) * 144B
#define P_B_OFF 18432                   // A occupies 128*144
#define GSMEM_P (NSTAGE*P_STG_BYTES)    // 165888

__global__ __launch_bounds__(256)
void gemm_proj(const float* __restrict__ p0){
    extern __shared__ char smem[];
    const uint32_t sbase = s2u(smem);

    const int tid = threadIdx.x, wid = tid>>5, lane = tid&31;
    const int wm = wid & 1, wn = wid >> 1;        // 2x4 warps of 64x64
    const int nt = blockIdx.x, mt = blockIdx.y;   // nt: 0..4 (256 cols each = one matq)

    const __half* Ab = a_pk + (size_t)(mt*128)*256;
    const __half* Bb = b_pk + (size_t)(nt*256)*256;

    float acc[4][8][4];
    #pragma unroll
    for(int i=0;i<4;i++)
        #pragma unroll
        for(int j=0;j<8;j++)
            #pragma unroll
            for(int k=0;k<4;k++) acc[i][j][k]=0.f;

    auto issue_stage = [&](int c){
        const uint32_t stg = sbase + (uint32_t)(c % NSTAGE)*P_STG_BYTES;
        const __half* ac = Ab + c*64;
        const __half* bc = Bb + c*64;
        #pragma unroll
        for(int t=0;t<4;t++){
            int idx = tid + t*256;
            int r = idx>>3, cc = idx&7;
            uint32_t sa = stg + r*144 + cc*16;
            const void* ga = ac + (size_t)r*256 + cc*8;
            asm volatile("cp.async.cg.shared.global [%0], [%1], 16;"::"r"(sa),"l"(ga));
        }
        #pragma unroll
        for(int t=0;t<8;t++){
            int idx = tid + t*256;
            int r = idx>>3, cc = idx&7;
            uint32_t sb = stg + P_B_OFF + r*144 + cc*16;
            const void* gb = bc + (size_t)r*256 + cc*8;
            asm volatile("cp.async.cg.shared.global [%0], [%1], 16;"::"r"(sb),"l"(gb));
        }
        asm volatile("cp.async.commit_group;");
    };

    issue_stage(0);
    issue_stage(1);

    for(int c = 0; c < 4; c++){
        if(c < 3) asm volatile("cp.async.wait_group 1;");
        else      asm volatile("cp.async.wait_group 0;");
        __syncthreads();
        if(c+2 < 4) issue_stage(c+2);

        const uint32_t stg = sbase + (uint32_t)(c % NSTAGE)*P_STG_BYTES;
        const uint32_t abase = stg;
        const uint32_t bbase = stg + P_B_OFF;
        #pragma unroll
        for(int ks=0; ks<4; ks++){
            uint32_t ar[4][4];
            #pragma unroll
            for(int mi=0;mi<4;mi++){
                int row = wm*64 + mi*16 + (lane&15);
                uint32_t addr = abase + row*144 + ks*32 + (lane>>4)*16;
                asm volatile("ldmatrix.sync.aligned.m8n8.x4.shared.b16 {%0,%1,%2,%3}, [%4];"
                    : "=r"(ar[mi][0]),"=r"(ar[mi][1]),"=r"(ar[mi][2]),"=r"(ar[mi][3])
                    : "r"(addr));
            }
            uint32_t br[4][4];
            #pragma unroll
            for(int nb=0;nb<4;nb++){
                int nrow = wn*64 + nb*16 + (lane&7) + ((lane>>4)&1)*8;
                uint32_t addr = bbase + nrow*144 + ks*32 + ((lane>>3)&1)*16;
                asm volatile("ldmatrix.sync.aligned.m8n8.x4.shared.b16 {%0,%1,%2,%3}, [%4];"
                    : "=r"(br[nb][0]),"=r"(br[nb][1]),"=r"(br[nb][2]),"=r"(br[nb][3])
                    : "r"(addr));
            }
            #pragma unroll
            for(int mi=0;mi<4;mi++)
                #pragma unroll
                for(int ni=0;ni<8;ni++){
                    uint32_t b0 = br[ni>>1][(ni&1)*2];
                    uint32_t b1 = br[ni>>1][(ni&1)*2+1];
                    float* cc2 = acc[mi][ni];
                    asm volatile(
                        "mma.sync.aligned.m16n8k16.row.col.f32.f16.f16.f32 "
                        "{%0,%1,%2,%3}, {%4,%5,%6,%7}, {%8,%9}, {%0,%1,%2,%3};"
                        : "+f"(cc2[0]),"+f"(cc2[1]),"+f"(cc2[2]),"+f"(cc2[3])
                        : "r"(ar[mi][0]),"r"(ar[mi][1]),"r"(ar[mi][2]),"r"(ar[mi][3]),
                          "r"(b0),"r"(b1));
                }
        }
        __syncthreads();
    }

    // epilogue: two half-passes (128 columns each) through smem [128][129] fp32
    const int grow = lane>>2, gcol = (lane&3)*2;
    float* st = (float*)smem;
    const int n  = (mt*128)/LR;
    const int l0 = (mt*128)%LR;
    const int matq = nt;

    #pragma unroll
    for(int g=0; g<2; g++){
        if((wn>>1) == g){
            #pragma unroll
            for(int mi=0;mi<4;mi++)
                #pragma unroll
                for(int ni=0;ni<8;ni++){
                    int r = wm*64 + mi*16 + grow;
                    int cc = (wn&1)*64 + ni*8 + gcol;
                    st[r*129 + cc]       = acc[mi][ni][0];
                    st[r*129 + cc+1]     = acc[mi][ni][1];
                    st[(r+8)*129 + cc]   = acc[mi][ni][2];
                    st[(r+8)*129 + cc+1] = acc[mi][ni][3];
                }
        }
        __syncthreads();
        const int cl0 = g*128;
        if(matq==2){
            if(tid < 128){
                int cl = cl0 + tid;
                int h = cl>>5, d = cl&31;
                __half* dst = &vt_pk[((size_t)(h*NS*DHH) + n*DHH + d)*LR + l0];
                for(int l=0;l<128;l+=2){
                    __half2 hv = __floats2half2_rn(st[l*129+tid], st[(l+1)*129+tid]);
                    *(__half2*)&dst[l] = hv;
                }
            }
        } else {
            for(int seg = tid; seg < 512; seg += 256){
                int l = seg >> 2, hh = seg & 3;
                int cl = cl0 + hh*32;
                int h = cl>>5;
                const float* srow = &st[l*129 + hh*32];
                if(matq==0){
                    __half2* dst = (__half2*)&q_pk[((size_t)h*LR + l0+l)*8192 + n*DHH];
                    #pragma unroll
                    for(int d2=0; d2<16; d2++)
                        dst[d2] = __floats2half2_rn(srow[d2*2], srow[d2*2+1]);
                } else if(matq==1){
                    __half2* dst = (__half2*)&k_pk[((size_t)h*LR + l0+l)*8192 + n*DHH];
                    #pragma unroll
                    for(int d2=0; d2<16; d2++)
                        dst[d2] = __floats2half2_rn(srow[d2*2]*SCALE_DH, srow[d2*2+1]*SCALE_DH);
                } else if(matq==3){
                    __half2* dst = (__half2*)&g_gate[(size_t)(n*LR + l0+l)*HDM + cl];
                    #pragma unroll
                    for(int d2=0; d2<16; d2++){
                        float v0 = __frcp_rn(1.f + __expf(-(srow[d2*2]   + p0[cl+d2*2])));
                        float v1 = __frcp_rn(1.f + __expf(-(srow[d2*2+1] + p0[cl+d2*2+1])));
                        dst[d2] = __floats2half2_rn(v0, v1);
                    }
                } else {
                    // seq logits: each half-pass covers DISJOINT heads (g=0: h0-3, g=1: h4-7)
                    // -> plain store seeded from lbias; written exactly once per launch.
                    int lg = l0 + l;
                    const float* sq = &g_swq[lg*HDM + cl];
                    float pv = g_lbias[lg*NH + h];
                    #pragma unroll
                    for(int d=0; d<32; d++) pv += sq[d]*srow[d];
                    g_logit[(lg*NH + h)*NS + n] = pv;
                }
            }
        }
        __syncthreads();
    }
}

// ---------------- mma.sync fp16 GEMM: BM=BN=128, 4 warps x (64x64), 3-stage cp.async ----------------
template<int MODE>
__global__ __launch_bounds__(128)
void gemm_mma(const float* __restrict__ p0, float* __restrict__ outp){
    constexpr int KR  = (MODE==1) ? 8192 : (MODE==2) ? 384 : 256;
    constexpr int KRL = (MODE==1) ? 2048 : KR;
    constexpr int Cn  = KRL/64;

    extern __shared__ char smem[];
    const uint32_t sbase = s2u(smem);

    const int tid = threadIdx.x, wid = tid>>5, lane = tid&31;
    const int wm = wid & 1, wn = wid >> 1;
    const int nt = blockIdx.x, mt = blockIdx.y, z = blockIdx.z;

    const __half* A; const __half* B;
    size_t saz = 0, sbz = 0;
    if(MODE==1){ A = q_pk; B = k_pk; saz = (size_t)LR*8192; sbz = (size_t)LR*8192; }
    else if(MODE==2){ A = p_pk; B = vt_pk; saz = (size_t)LR*384; sbz = (size_t)NS*DHH*LR; }
    else { A = a_pk; B = wo_pk; }

    const int zz    = (MODE==1) ? (z>>2) : z;
    const int kbase = (MODE==1) ? (z&3)*KRL : 0;

    const __half* Ab = A + saz*zz + (size_t)(mt*128)*KR;
    const __half* Bb = B + sbz*zz + (size_t)(nt*128)*KR;

    float acc[4][8][4];
    #pragma unroll
    for(int i=0;i<4;i++)
        #pragma unroll
        for(int j=0;j<8;j++)
            #pragma unroll
            for(int k=0;k<4;k++) acc[i][j][k]=0.f;

    auto issue_stage = [&](int c){
        const uint32_t stg = sbase + (uint32_t)(c % NSTAGE)*STG_BYTES;
        const int off = kbase + c*64;
        const __half* ac = Ab + off;
        const __half* bc = Bb + off;
        #pragma unroll
        for(int t=0;t<8;t++){
            int idx = tid + t*128;
            int r = idx>>3, cc = idx&7;
            uint32_t sa = stg + r*144 + cc*16;
            const void* ga = ac + (size_t)r*KR + cc*8;
            asm volatile("cp.async.cg.shared.global [%0], [%1], 16;"::"r"(sa),"l"(ga));
        }
        #pragma unroll
        for(int t=0;t<8;t++){
            int idx = tid + t*128;
            int r = idx>>3, cc = idx&7;
            uint32_t sb = stg + B_OFF_BYTES + r*144 + cc*16;
            const void* gb = bc + (size_t)r*KR + cc*8;
            asm volatile("cp.async.cg.shared.global [%0], [%1], 16;"::"r"(sb),"l"(gb));
        }
        asm volatile("cp.async.commit_group;");
    };

    issue_stage(0);
    if(Cn > 1) issue_stage(1);

    for(int c = 0; c < Cn; c++){
        if(c < Cn-1) asm volatile("cp.async.wait_group 1;");
        else         asm volatile("cp.async.wait_group 0;");
        __syncthreads();
        if(c+2 < Cn) issue_stage(c+2);

        const uint32_t stg = sbase + (uint32_t)(c % NSTAGE)*STG_BYTES;
        const uint32_t abase = stg;
        const uint32_t bbase = stg + B_OFF_BYTES;
        #pragma unroll
        for(int ks=0; ks<4; ks++){
            uint32_t ar[4][4];
            #pragma unroll
            for(int mi=0;mi<4;mi++){
                int row = wm*64 + mi*16 + (lane&15);
                uint32_t addr = abase + row*144 + ks*32 + (lane>>4)*16;
                asm volatile("ldmatrix.sync.aligned.m8n8.x4.shared.b16 {%0,%1,%2,%3}, [%4];"
                    : "=r"(ar[mi][0]),"=r"(ar[mi][1]),"=r"(ar[mi][2]),"=r"(ar[mi][3])
                    : "r"(addr));
            }
            uint32_t br[4][4];
            #pragma unroll
            for(int nb=0;nb<4;nb++){
                int nrow = wn*64 + nb*16 + (lane&7) + ((lane>>4)&1)*8;
                uint32_t addr = bbase + nrow*144 + ks*32 + ((lane>>3)&1)*16;
                asm volatile("ldmatrix.sync.aligned.m8n8.x4.shared.b16 {%0,%1,%2,%3}, [%4];"
                    : "=r"(br[nb][0]),"=r"(br[nb][1]),"=r"(br[nb][2]),"=r"(br[nb][3])
                    : "r"(addr));
            }
            #pragma unroll
            for(int mi=0;mi<4;mi++)
                #pragma unroll
                for(int ni=0;ni<8;ni++){
                    uint32_t b0 = br[ni>>1][(ni&1)*2];
                    uint32_t b1 = br[ni>>1][(ni&1)*2+1];
                    float* cc2 = acc[mi][ni];
                    asm volatile(
                        "mma.sync.aligned.m16n8k16.row.col.f32.f16.f16.f32 "
                        "{%0,%1,%2,%3}, {%4,%5,%6,%7}, {%8,%9}, {%0,%1,%2,%3};"
                        : "+f"(cc2[0]),"+f"(cc2[1]),"+f"(cc2[2]),"+f"(cc2[3])
                        : "r"(ar[mi][0]),"r"(ar[mi][1]),"r"(ar[mi][2]),"r"(ar[mi][3]),
                          "r"(b0),"r"(b1));
                }
        }
        __syncthreads();
    }

    const int grow = lane>>2, gcol = (lane&3)*2;

    if(MODE==1){
        #pragma unroll
        for(int mi=0;mi<4;mi++)
            #pragma unroll
            for(int ni=0;ni<8;ni++){
                int R0 = mt*128 + wm*64 + mi*16 + grow;
                int C0 = nt*128 + wn*64 + ni*8 + gcol;
                atomicAdd(&g_attn[zz*LL + R0*LR + C0],       acc[mi][ni][0]);
                atomicAdd(&g_attn[zz*LL + R0*LR + C0+1],     acc[mi][ni][1]);
                atomicAdd(&g_attn[zz*LL + (R0+8)*LR + C0],   acc[mi][ni][2]);
                atomicAdd(&g_attn[zz*LL + (R0+8)*LR + C0+1], acc[mi][ni][3]);
            }
        return;
    }
    if(MODE==3){
        #pragma unroll
        for(int mi=0;mi<4;mi++)
            #pragma unroll
            for(int ni=0;ni<8;ni++){
                int R0 = mt*128 + wm*64 + mi*16 + grow;
                int C0 = nt*128 + wn*64 + ni*8 + gcol;
                outp[R0*DM + C0]       = acc[mi][ni][0] + p0[C0];
                outp[R0*DM + C0+1]     = acc[mi][ni][1] + p0[C0+1];
                outp[(R0+8)*DM + C0]   = acc[mi][ni][2] + p0[C0];
                outp[(R0+8)*DM + C0+1] = acc[mi][ni][3] + p0[C0+1];
            }
        return;
    }

    // MODE 2 staged epilogue: gate + pack into a_pk
    float* st = (float*)smem;
    #pragma unroll
    for(int mi=0;mi<4;mi++)
        #pragma unroll
        for(int ni=0;ni<8;ni++){
            int r = wm*64 + mi*16 + grow;
            int cc = wn*64 + ni*8 + gcol;
            st[r*129 + cc]       = acc[mi][ni][0];
            st[r*129 + cc+1]     = acc[mi][ni][1];
            st[(r+8)*129 + cc]   = acc[mi][ni][2];
            st[(r+8)*129 + cc+1] = acc[mi][ni][3];
        }
    __syncthreads();

    for(int seg = tid; seg < 512; seg += 128){
        int q = seg>>2, ss = seg&3;
        int s = nt*4 + ss;
        size_t rr = (size_t)s*LR + mt*128 + q;
        const __half2* gr = (const __half2*)&g_gate[rr*HDM + z*DHH];
        const float* srow = &st[q*129 + ss*32];
        __half2* dst = (__half2*)&a_pk[rr*256 + z*DHH];
        #pragma unroll
        for(int d2=0; d2<16; d2++){
            float2 g2 = __half22float2(gr[d2]);
            dst[d2] = __floats2half2_rn(srow[d2*2]*g2.x, srow[d2*2+1]*g2.y);
        }
    }
}

// ---------------- 5. softmax over n + scale q_pk in place ----------------
__global__ void seq_softmax_kernel(){
    __shared__ float sh[8];
    __shared__ float wsh[NS];
    int l = blockIdx.x >> 3, h = blockIdx.x & 7;
    int tid = threadIdx.x;
    float x = g_logit[(l*NH+h)*NS + tid];
    float m = warpMax(x);
    if((tid&31)==0) sh[tid>>5]=m;
    __syncthreads();
    if(tid<32){ float mm=(tid<8)?sh[tid]:-1e30f; mm=warpMax(mm); if(tid==0) sh[0]=mm; }
    __syncthreads();
    m = sh[0];
    __syncthreads();
    float e = __expf(x - m);
    float s = warpRed(e);
    if((tid&31)==0) sh[tid>>5]=s;
    __syncthreads();
    if(tid<32){ float ss=(tid<8)?sh[tid]:0.f; ss=warpRed(ss); if(tid==0) sh[0]=ss; }
    __syncthreads();
    s = sh[0];
    wsh[tid] = e * __frcp_rn(s);
    __syncthreads();
    __half2* qp = (__half2*)(q_pk + (size_t)(h*LR + l)*8192);
    for(int i=tid; i<4096; i+=256){
        float w = wsh[i>>4];
        float2 v = __half22float2(qp[i]);
        qp[i] = __floats2half2_rn(v.x*w, v.y*w);
    }
}

// ---------------- 6. pair bias = LN(pair) @ wb -> seeds g_attn ----------------
__global__ void bias_kernel(const float* __restrict__ pair, const float* __restrict__ g,
                            const float* __restrict__ b, const float* __restrict__ wb){
    __shared__ float wbs[NH][DP];
    int tid = threadIdx.x;
    for(int idx=tid; idx<NH*DP; idx+=256){
        int h = idx / DP, k = idx % DP;
        wbs[h][k] = wb[k*NH + h];
    }
    __syncthreads();
    int warp = tid >> 5, lane = tid & 31;
    int p = blockIdx.x*8 + warp;
    float4 xv = ((const float4*)(pair + (size_t)p*DP))[lane];
    float sum = xv.x+xv.y+xv.z+xv.w;
    float sq  = xv.x*xv.x+xv.y*xv.y+xv.z*xv.z+xv.w*xv.w;
    sum = warpRed(sum); sq = warpRed(sq);
    float mean = sum*(1.f/DP);
    float var  = sq*(1.f/DP) - mean*mean;
    float inv  = rsqrtf(var + 1e-5f);
    float4 gv = ((const float4*)g)[lane];
    float4 bv = ((const float4*)b)[lane];
    float xn0 = (xv.x-mean)*inv*gv.x + bv.x;
    float xn1 = (xv.y-mean)*inv*gv.y + bv.y;
    float xn2 = (xv.z-mean)*inv*gv.z + bv.z;
    float xn3 = (xv.w-mean)*inv*gv.w + bv.w;
    #pragma unroll
    for(int h=0;h<NH;h++){
        float4 wv4 = ((const float4*)(wbs[h]))[lane];
        float prt = xn0*wv4.x + xn1*wv4.y + xn2*wv4.z + xn3*wv4.w;
        prt = warpRed(prt);
        if(lane==0) g_attn[h*LL + p] = prt;
    }
}

// ---------------- 8. softmax over k -> p_pk fp16 ----------------
__global__ void attn_softmax_kernel(){
    __shared__ float sh[4];
    int row = blockIdx.x;
    const float* a = g_attn + (size_t)row*LR;
    int tid = threadIdx.x;
    float x0 = a[tid];
    float x1 = a[tid+128];
    float x2 = a[tid+256];
    float m = fmaxf(x0, fmaxf(x1, x2));
    m = warpMax(m);
    if((tid&31)==0) sh[tid>>5]=m;
    __syncthreads();
    if(tid<32){ float mm=(tid<4)?sh[tid]:-1e30f; mm=warpMax(mm); if(tid==0) sh[0]=mm; }
    __syncthreads();
    m = sh[0];
    __syncthreads();
    x0 = __expf(x0-m); x1 = __expf(x1-m); x2 = __expf(x2-m);
    float s = warpRed(x0+x1+x2);
    if((tid&31)==0) sh[tid>>5]=s;
    __syncthreads();
    if(tid<32){ float ss=(tid<4)?sh[tid]:0.f; ss=warpRed(ss); if(tid==0) sh[0]=ss; }
    __syncthreads();
    s = sh[0];
    float rcp = __frcp_rn(s);
    __half* pp = p_pk + (size_t)row*384;
    pp[tid]     = __float2half(x0*rcp);
    pp[tid+128] = __float2half(x1*rcp);
    pp[tid+256] = __float2half(x2*rcp);
}

// ---------------- launch ----------------
extern "C" void kernel_launch(void* const* d_in, const int* in_sizes, int n_in,
                              void* d_out, int out_size){
    const float* msa       = (const float*)d_in[0];
    const float* pair      = (const float*)d_in[1];
    const float* ln_msa_g  = (const float*)d_in[2];
    const float* ln_msa_b  = (const float*)d_in[3];
    const float* ln_pair_g = (const float*)d_in[4];
    const float* ln_pair_b = (const float*)d_in[5];
    const float* sw_q_w    = (const float*)d_in[6];
    const float* sw_q_b    = (const float*)d_in[7];
    const float* sw_k_w    = (const float*)d_in[8];
    const float* sw_k_b    = (const float*)d_in[9];
    const float* wq        = (const float*)d_in[10];
    const float* wk        = (const float*)d_in[11];
    const float* wv        = (const float*)d_in[12];
    const float* wb        = (const float*)d_in[13];
    const float* wg        = (const float*)d_in[14];
    const float* bg        = (const float*)d_in[15];
    const float* wo        = (const float*)d_in[16];
    const float* bo        = (const float*)d_in[17];
    float* out = (float*)d_out;

    static cudaStream_t s2 = nullptr;
    static cudaEvent_t evFork = nullptr, evPack = nullptr, evBias = nullptr;
    if(s2 == nullptr){
        cudaStreamCreateWithFlags(&s2, cudaStreamNonBlocking);
        cudaEventCreateWithFlags(&evFork, cudaEventDisableTiming);
        cudaEventCreateWithFlags(&evPack, cudaEventDisableTiming);
        cudaEventCreateWithFlags(&evBias, cudaEventDisableTiming);
    }

    cudaFuncSetAttribute(gemm_proj,   cudaFuncAttributeMaxDynamicSharedMemorySize, GSMEM_P);
    cudaFuncSetAttribute(gemm_mma<1>, cudaFuncAttributeMaxDynamicSharedMemorySize, GSMEM_BYTES);
    cudaFuncSetAttribute(gemm_mma<2>, cudaFuncAttributeMaxDynamicSharedMemorySize, GSMEM_BYTES);
    cudaFuncSetAttribute(gemm_mma<3>, cudaFuncAttributeMaxDynamicSharedMemorySize, GSMEM_BYTES);

    // fork side stream off the (possibly capturing) null stream
    cudaEventRecord(evFork, 0);
    cudaStreamWaitEvent(s2, evFork, 0);

    // side stream: weight packing, then pair bias (independent of main chain)
    pack_w_kernel<<<1536, 256, 0, s2>>>(wq, wk, wv, wg, sw_k_w, wo);
    cudaEventRecord(evPack, s2);
    bias_kernel<<<LL/8, 256, 0, s2>>>(pair, ln_pair_g, ln_pair_b, wb);   // seeds g_attn
    cudaEventRecord(evBias, s2);

    // main stream
    ln_msa_kernel<<<NL/8, 256>>>(msa, ln_msa_g, ln_msa_b);
    swq_kernel<<<LR, 256>>>(sw_q_w, sw_q_b, sw_k_b);

    cudaStreamWaitEvent(0, evPack, 0);   // proj needs b_pk
    // proj: [98304 x 1280], K=256, BN=256 tile
    gemm_proj<<<dim3(5, 768), 256, GSMEM_P>>>(bg);

    seq_softmax_kernel<<<LR*NH, 256>>>();

    cudaStreamWaitEvent(0, evBias, 0);   // qk accumulates onto bias-seeded g_attn
    gemm_mma<1><<<dim3(3, 3, NH*4), 128, GSMEM_BYTES>>>(nullptr, nullptr);

    attn_softmax_kernel<<<NH*LR, 128>>>();

    gemm_mma<2><<<dim3(64, 3, NH), 128, GSMEM_BYTES>>>(nullptr, nullptr);

    gemm_mma<3><<<dim3(2, 768, 1), 128, GSMEM_BYTES>>>(bo, out);
}

// round 17
// speedup vs baseline: 1.0320x; 1.0320x over previous
#include <cuda_runtime.h>
#include <cuda_fp16.h>
#include <math.h>
#include <stdint.h>

// Problem constants
#define NS 256
#define LR 384
#define DM 256
#define DP 128
#define NH 8
#define DHH 32
#define HDM 256
#define NL (NS*LR)      // 98304
#define LL (LR*LR)      // 147456
#define SCALE_DH 0.17677669529663687f

// ---------------- device scratch ----------------
__device__ float g_swq[LR*HDM];
__device__ float g_lbias[LR*NH];
__device__ __half g_gate[NL*HDM];
__device__ float g_logit[LR*NH*NS];
__device__ float g_attn[NH*LL];           // pair bias, then += qk logits (split-K atomics)

// packed fp16 operands
__device__ __half a_pk[(size_t)NL*256];            // [r][256]: msan (proj) / gated-out (out)
__device__ __half b_pk[1280*256];                  // proj weights^T, [n][256]
__device__ __half wo_pk[DM*256];                   // wo^T, [n][256]
__device__ __half q_pk[(size_t)NH*LR*8192];        // [h*384+l][n*32+d], raw then weighted
__device__ __half k_pk[(size_t)NH*LR*8192];        // [h*384+l][n*32+d]
__device__ __half vt_pk[(size_t)NH*NS*DHH*LR];     // [h*8192+(s*32+d)][l]
__device__ __half p_pk[(size_t)NH*LR*384];         // [h*384+q][k]

// ---------------- helpers ----------------
__device__ __forceinline__ float warpRed(float v){
    #pragma unroll
    for(int o=16;o>0;o>>=1) v += __shfl_xor_sync(0xffffffffu, v, o);
    return v;
}
__device__ __forceinline__ float warpMax(float v){
    #pragma unroll
    for(int o=16;o>0;o>>=1) v = fmaxf(v, __shfl_xor_sync(0xffffffffu, v, o));
    return v;
}
__device__ __forceinline__ uint32_t s2u(const void* p){
    uint32_t a; asm("{ .reg .u64 t; cvta.to.shared.u64 t, %1; cvt.u32.u64 %0, t; }" : "=r"(a) : "l"(p));
    return a;
}

// ---------------- 1. LayerNorm of msa + pack A (warp per row) ----------------
__global__ void ln_msa_kernel(const float* __restrict__ x,
                              const float* __restrict__ gg,
                              const float* __restrict__ bb){
    int warp = threadIdx.x>>5, lane = threadIdx.x&31;
    int row = blockIdx.x*8 + warp;
    const float4* xr = (const float4*)(x + (size_t)row*DM);
    float4 v0 = xr[lane], v1 = xr[lane+32];
    float sum = v0.x+v0.y+v0.z+v0.w + v1.x+v1.y+v1.z+v1.w;
    float sq  = v0.x*v0.x+v0.y*v0.y+v0.z*v0.z+v0.w*v0.w
              + v1.x*v1.x+v1.y*v1.y+v1.z*v1.z+v1.w*v1.w;
    sum = warpRed(sum); sq = warpRed(sq);
    float mean = sum*(1.f/DM);
    float var  = sq*(1.f/DM) - mean*mean;
    float inv  = rsqrtf(var + 1e-5f);
    float4 g0 = ((const float4*)gg)[lane], g1 = ((const float4*)gg)[lane+32];
    float4 b0 = ((const float4*)bb)[lane], b1 = ((const float4*)bb)[lane+32];
    float y0 = (v0.x-mean)*inv*g0.x + b0.x;
    float y1 = (v0.y-mean)*inv*g0.y + b0.y;
    float y2 = (v0.z-mean)*inv*g0.z + b0.z;
    float y3 = (v0.w-mean)*inv*g0.w + b0.w;
    float y4 = (v1.x-mean)*inv*g1.x + b1.x;
    float y5 = (v1.y-mean)*inv*g1.y + b1.y;
    float y6 = (v1.z-mean)*inv*g1.z + b1.z;
    float y7 = (v1.w-mean)*inv*g1.w + b1.w;
    __half2* ap = (__half2*)(a_pk + (size_t)row*256);
    ap[lane*2]      = __floats2half2_rn(y0,y1);
    ap[lane*2+1]    = __floats2half2_rn(y2,y3);
    ap[64+lane*2]   = __floats2half2_rn(y4,y5);
    ap[64+lane*2+1] = __floats2half2_rn(y6,y7);
}

// ---------------- 2. pack weights (transposed, single fp16) ----------------
__global__ void pack_w_kernel(const float* __restrict__ wq, const float* __restrict__ wk,
                              const float* __restrict__ wv, const float* __restrict__ wg,
                              const float* __restrict__ wsk, const float* __restrict__ wo){
    int n = blockIdx.x, k = threadIdx.x;
    if(n < 1280){
        int mat = n >> 8, nl = n & 255;
        const float* W = (mat==0)?wq:(mat==1)?wk:(mat==2)?wv:(mat==3)?wg:wsk;
        b_pk[n*256 + k] = __float2half(W[k*HDM + nl]);
    } else {
        int nl = n - 1280;
        wo_pk[nl*256 + k] = __float2half(wo[k*DM + nl]);
    }
}

// ---------------- 3. swq: self-contained LN(msa row l) -> GEMV (+ fused lbias) ----------------
__global__ void swq_kernel(const float* __restrict__ x,
                           const float* __restrict__ lng, const float* __restrict__ lnb,
                           const float* __restrict__ W, const float* __restrict__ bqb,
                           const float* __restrict__ skb){
    __shared__ float t[DM];
    __shared__ float s1[8], s2v[8];
    int l = blockIdx.x, tid = threadIdx.x, lane = tid&31;
    float v = x[l*DM + tid];            // n=0 rows are rows 0..383 of msa
    float a = warpRed(v);
    float b = warpRed(v*v);
    if(lane==0){ s1[tid>>5]=a; s2v[tid>>5]=b; }
    __syncthreads();
    if(tid<32){
        float aa = (tid<8)? s1[tid] : 0.f;
        float bb2 = (tid<8)? s2v[tid] : 0.f;
        aa = warpRed(aa); bb2 = warpRed(bb2);
        if(tid==0){ s1[0]=aa; s2v[0]=bb2; }
    }
    __syncthreads();
    float mean = s1[0]*(1.f/DM);
    float var  = s2v[0]*(1.f/DM) - mean*mean;
    float inv  = rsqrtf(var + 1e-5f);
    t[tid] = (v-mean)*inv*lng[tid] + lnb[tid];
    __syncthreads();
    float acc = 0.f;
    #pragma unroll 8
    for(int k=0;k<DM;k++) acc += t[k]*W[k*HDM + tid];
    float val = (acc + bqb[tid]) * SCALE_DH;
    g_swq[l*HDM + tid] = val;
    float pv = val * skb[tid];
    pv = warpRed(pv);
    if(lane==0) g_lbias[l*NH + (tid>>5)] = pv;
}

// ---------------- mma.sync fp16 GEMM: BM=BN=128, 4 warps x (64x64), 3-stage cp.async ----------------
// MODE 0: proj  A=a_pk[NL x 256],     B=b_pk[1280 x 256]   (staged epilogue + logits)
// MODE 1: qk    A=q_pk[h][384x8192],  B=k_pk[h][384x8192]  (split-K x4, atomicAdd onto bias)
// MODE 2: av    A=p_pk[h][384x384],   B=vt_pk[h][8192x384] (staged: gate + a_pk)
// MODE 3: out   A=a_pk[NL x 256],     B=wo_pk[256 x 256]   (direct)
#define STG_BYTES 36864
#define B_OFF_BYTES 18432
#define NSTAGE 3
#define GSMEM_BYTES (NSTAGE*STG_BYTES)  // 110592

template<int MODE>
__global__ __launch_bounds__(128)
void gemm_mma(const float* __restrict__ p0, float* __restrict__ outp){
    constexpr int KR  = (MODE==1) ? 8192 : (MODE==2) ? 384 : 256;
    constexpr int KRL = (MODE==1) ? 2048 : KR;
    constexpr int Cn  = KRL/64;

    extern __shared__ char smem[];
    const uint32_t sbase = s2u(smem);

    const int tid = threadIdx.x, wid = tid>>5, lane = tid&31;
    const int wm = wid & 1, wn = wid >> 1;
    const int nt = blockIdx.x, mt = blockIdx.y, z = blockIdx.z;

    const __half* A; const __half* B;
    size_t saz = 0, sbz = 0;
    if(MODE==0){ A = a_pk;  B = b_pk; }
    else if(MODE==1){ A = q_pk; B = k_pk; saz = (size_t)LR*8192; sbz = (size_t)LR*8192; }
    else if(MODE==2){ A = p_pk; B = vt_pk; saz = (size_t)LR*384; sbz = (size_t)NS*DHH*LR; }
    else { A = a_pk; B = wo_pk; }

    const int zz    = (MODE==1) ? (z>>2) : z;
    const int kbase = (MODE==1) ? (z&3)*KRL : 0;

    const __half* Ab = A + saz*zz + (size_t)(mt*128)*KR;
    const __half* Bb = B + sbz*zz + (size_t)(nt*128)*KR;

    float acc[4][8][4];
    #pragma unroll
    for(int i=0;i<4;i++)
        #pragma unroll
        for(int j=0;j<8;j++)
            #pragma unroll
            for(int k=0;k<4;k++) acc[i][j][k]=0.f;

    auto issue_stage = [&](int c){
        const uint32_t stg = sbase + (uint32_t)(c % NSTAGE)*STG_BYTES;
        const int off = kbase + c*64;
        const __half* ac = Ab + off;
        const __half* bc = Bb + off;
        #pragma unroll
        for(int t=0;t<8;t++){
            int idx = tid + t*128;
            int r = idx>>3, cc = idx&7;
            uint32_t sa = stg + r*144 + cc*16;
            const void* ga = ac + (size_t)r*KR + cc*8;
            asm volatile("cp.async.cg.shared.global [%0], [%1], 16;"::"r"(sa),"l"(ga));
        }
        #pragma unroll
        for(int t=0;t<8;t++){
            int idx = tid + t*128;
            int r = idx>>3, cc = idx&7;
            uint32_t sb = stg + B_OFF_BYTES + r*144 + cc*16;
            const void* gb = bc + (size_t)r*KR + cc*8;
            asm volatile("cp.async.cg.shared.global [%0], [%1], 16;"::"r"(sb),"l"(gb));
        }
        asm volatile("cp.async.commit_group;");
    };

    issue_stage(0);
    if(Cn > 1) issue_stage(1);

    for(int c = 0; c < Cn; c++){
        if(c < Cn-1) asm volatile("cp.async.wait_group 1;");
        else         asm volatile("cp.async.wait_group 0;");
        __syncthreads();
        if(c+2 < Cn) issue_stage(c+2);

        const uint32_t stg = sbase + (uint32_t)(c % NSTAGE)*STG_BYTES;
        const uint32_t abase = stg;
        const uint32_t bbase = stg + B_OFF_BYTES;
        #pragma unroll
        for(int ks=0; ks<4; ks++){
            uint32_t ar[4][4];
            #pragma unroll
            for(int mi=0;mi<4;mi++){
                int row = wm*64 + mi*16 + (lane&15);
                uint32_t addr = abase + row*144 + ks*32 + (lane>>4)*16;
                asm volatile("ldmatrix.sync.aligned.m8n8.x4.shared.b16 {%0,%1,%2,%3}, [%4];"
                    : "=r"(ar[mi][0]),"=r"(ar[mi][1]),"=r"(ar[mi][2]),"=r"(ar[mi][3])
                    : "r"(addr));
            }
            uint32_t br[4][4];
            #pragma unroll
            for(int nb=0;nb<4;nb++){
                int nrow = wn*64 + nb*16 + (lane&7) + ((lane>>4)&1)*8;
                uint32_t addr = bbase + nrow*144 + ks*32 + ((lane>>3)&1)*16;
                asm volatile("ldmatrix.sync.aligned.m8n8.x4.shared.b16 {%0,%1,%2,%3}, [%4];"
                    : "=r"(br[nb][0]),"=r"(br[nb][1]),"=r"(br[nb][2]),"=r"(br[nb][3])
                    : "r"(addr));
            }
            #pragma unroll
            for(int mi=0;mi<4;mi++)
                #pragma unroll
                for(int ni=0;ni<8;ni++){
                    uint32_t b0 = br[ni>>1][(ni&1)*2];
                    uint32_t b1 = br[ni>>1][(ni&1)*2+1];
                    float* cc2 = acc[mi][ni];
                    asm volatile(
                        "mma.sync.aligned.m16n8k16.row.col.f32.f16.f16.f32 "
                        "{%0,%1,%2,%3}, {%4,%5,%6,%7}, {%8,%9}, {%0,%1,%2,%3};"
                        : "+f"(cc2[0]),"+f"(cc2[1]),"+f"(cc2[2]),"+f"(cc2[3])
                        : "r"(ar[mi][0]),"r"(ar[mi][1]),"r"(ar[mi][2]),"r"(ar[mi][3]),
                          "r"(b0),"r"(b1));
                }
        }
        __syncthreads();
    }

    const int grow = lane>>2, gcol = (lane&3)*2;

    if(MODE==1){
        #pragma unroll
        for(int mi=0;mi<4;mi++)
            #pragma unroll
            for(int ni=0;ni<8;ni++){
                int R0 = mt*128 + wm*64 + mi*16 + grow;
                int C0 = nt*128 + wn*64 + ni*8 + gcol;
                atomicAdd(&g_attn[zz*LL + R0*LR + C0],       acc[mi][ni][0]);
                atomicAdd(&g_attn[zz*LL + R0*LR + C0+1],     acc[mi][ni][1]);
                atomicAdd(&g_attn[zz*LL + (R0+8)*LR + C0],   acc[mi][ni][2]);
                atomicAdd(&g_attn[zz*LL + (R0+8)*LR + C0+1], acc[mi][ni][3]);
            }
        return;
    }
    if(MODE==3){
        #pragma unroll
        for(int mi=0;mi<4;mi++)
            #pragma unroll
            for(int ni=0;ni<8;ni++){
                int R0 = mt*128 + wm*64 + mi*16 + grow;
                int C0 = nt*128 + wn*64 + ni*8 + gcol;
                outp[R0*DM + C0]       = acc[mi][ni][0] + p0[C0];
                outp[R0*DM + C0+1]     = acc[mi][ni][1] + p0[C0+1];
                outp[(R0+8)*DM + C0]   = acc[mi][ni][2] + p0[C0];
                outp[(R0+8)*DM + C0+1] = acc[mi][ni][3] + p0[C0+1];
            }
        return;
    }

    // staged epilogue (MODE 0 / MODE 2): accumulators -> smem [128][129] fp32
    float* st = (float*)smem;
    #pragma unroll
    for(int mi=0;mi<4;mi++)
        #pragma unroll
        for(int ni=0;ni<8;ni++){
            int r = wm*64 + mi*16 + grow;
            int cc = wn*64 + ni*8 + gcol;
            st[r*129 + cc]       = acc[mi][ni][0];
            st[r*129 + cc+1]     = acc[mi][ni][1];
            st[(r+8)*129 + cc]   = acc[mi][ni][2];
            st[(r+8)*129 + cc+1] = acc[mi][ni][3];
        }
    __syncthreads();

    if(MODE==0){
        const int n  = (mt*128)/LR;
        const int l0 = (mt*128)%LR;
        const int cg0 = nt*128;
        const int matq = cg0>>8;
        const int cl0 = cg0&255;
        if(matq==2){
            int cl = cl0 + tid;
            int h = cl>>5, d = cl&31;
            __half* dst = &vt_pk[((size_t)(h*NS*DHH) + n*DHH + d)*LR + l0];
            for(int l=0;l<128;l+=2){
                __half2 hv = __floats2half2_rn(st[l*129+tid], st[(l+1)*129+tid]);
                *(__half2*)&dst[l] = hv;
            }
        } else {
            for(int seg = tid; seg < 512; seg += 128){
                int l = seg >> 2, hh = seg & 3;
                int cl = cl0 + hh*32;
                int h = cl>>5;
                const float* srow = &st[l*129 + hh*32];
                if(matq==0){
                    __half2* dst = (__half2*)&q_pk[((size_t)h*LR + l0+l)*8192 + n*DHH];
                    #pragma unroll
                    for(int d2=0; d2<16; d2++)
                        dst[d2] = __floats2half2_rn(srow[d2*2], srow[d2*2+1]);
                } else if(matq==1){
                    __half2* dst = (__half2*)&k_pk[((size_t)h*LR + l0+l)*8192 + n*DHH];
                    #pragma unroll
                    for(int d2=0; d2<16; d2++)
                        dst[d2] = __floats2half2_rn(srow[d2*2]*SCALE_DH, srow[d2*2+1]*SCALE_DH);
                } else if(matq==3){
                    __half2* dst = (__half2*)&g_gate[(size_t)(n*LR + l0+l)*HDM + cl];
                    #pragma unroll
                    for(int d2=0; d2<16; d2++){
                        float v0 = __frcp_rn(1.f + __expf(-(srow[d2*2]   + p0[cl+d2*2])));
                        float v1 = __frcp_rn(1.f + __expf(-(srow[d2*2+1] + p0[cl+d2*2+1])));
                        dst[d2] = __floats2half2_rn(v0, v1);
                    }
                } else {
                    int lg = l0 + l;
                    const float* sq = &g_swq[lg*HDM + cl];
                    float pv = g_lbias[lg*NH + h];
                    #pragma unroll
                    for(int d=0; d<32; d++) pv += sq[d]*srow[d];
                    g_logit[(lg*NH + h)*NS + n] = pv;
                }
            }
        }
    } else {
        for(int seg = tid; seg < 512; seg += 128){
            int q = seg>>2, ss = seg&3;
            int s = nt*4 + ss;
            size_t rr = (size_t)s*LR + mt*128 + q;
            const __half2* gr = (const __half2*)&g_gate[rr*HDM + z*DHH];
            const float* srow = &st[q*129 + ss*32];
            __half2* dst = (__half2*)&a_pk[rr*256 + z*DHH];
            #pragma unroll
            for(int d2=0; d2<16; d2++){
                float2 g2 = __half22float2(gr[d2]);
                dst[d2] = __floats2half2_rn(srow[d2*2]*g2.x, srow[d2*2+1]*g2.y);
            }
        }
    }
}

// ---------------- 5. softmax over n + scale q_pk in place ----------------
__global__ void seq_softmax_kernel(){
    __shared__ float sh[8];
    __shared__ float wsh[NS];
    int l = blockIdx.x >> 3, h = blockIdx.x & 7;
    int tid = threadIdx.x;
    float x = g_logit[(l*NH+h)*NS + tid];
    float m = warpMax(x);
    if((tid&31)==0) sh[tid>>5]=m;
    __syncthreads();
    if(tid<32){ float mm=(tid<8)?sh[tid]:-1e30f; mm=warpMax(mm); if(tid==0) sh[0]=mm; }
    __syncthreads();
    m = sh[0];
    __syncthreads();
    float e = __expf(x - m);
    float s = warpRed(e);
    if((tid&31)==0) sh[tid>>5]=s;
    __syncthreads();
    if(tid<32){ float ss=(tid<8)?sh[tid]:0.f; ss=warpRed(ss); if(tid==0) sh[0]=ss; }
    __syncthreads();
    s = sh[0];
    wsh[tid] = e * __frcp_rn(s);
    __syncthreads();
    __half2* qp = (__half2*)(q_pk + (size_t)(h*LR + l)*8192);
    for(int i=tid; i<4096; i+=256){
        float w = wsh[i>>4];
        float2 v = __half22float2(qp[i]);
        qp[i] = __floats2half2_rn(v.x*w, v.y*w);
    }
}

// ---------------- 6. pair bias = LN(pair) @ wb -> seeds g_attn ----------------
__global__ void bias_kernel(const float* __restrict__ pair, const float* __restrict__ g,
                            const float* __restrict__ b, const float* __restrict__ wb){
    __shared__ float wbs[NH][DP];
    int tid = threadIdx.x;
    for(int idx=tid; idx<NH*DP; idx+=256){
        int h = idx / DP, k = idx % DP;
        wbs[h][k] = wb[k*NH + h];
    }
    __syncthreads();
    int warp = tid >> 5, lane = tid & 31;
    int p = blockIdx.x*8 + warp;
    float4 xv = ((const float4*)(pair + (size_t)p*DP))[lane];
    float sum = xv.x+xv.y+xv.z+xv.w;
    float sq  = xv.x*xv.x+xv.y*xv.y+xv.z*xv.z+xv.w*xv.w;
    sum = warpRed(sum); sq = warpRed(sq);
    float mean = sum*(1.f/DP);
    float var  = sq*(1.f/DP) - mean*mean;
    float inv  = rsqrtf(var + 1e-5f);
    float4 gv = ((const float4*)g)[lane];
    float4 bv = ((const float4*)b)[lane];
    float xn0 = (xv.x-mean)*inv*gv.x + bv.x;
    float xn1 = (xv.y-mean)*inv*gv.y + bv.y;
    float xn2 = (xv.z-mean)*inv*gv.z + bv.z;
    float xn3 = (xv.w-mean)*inv*gv.w + bv.w;
    #pragma unroll
    for(int h=0;h<NH;h++){
        float4 wv4 = ((const float4*)(wbs[h]))[lane];
        float prt = xn0*wv4.x + xn1*wv4.y + xn2*wv4.z + xn3*wv4.w;
        prt = warpRed(prt);
        if(lane==0) g_attn[h*LL + p] = prt;
    }
}

// ---------------- 8. softmax over k -> p_pk fp16 ----------------
__global__ void attn_softmax_kernel(){
    __shared__ float sh[4];
    int row = blockIdx.x;
    const float* a = g_attn + (size_t)row*LR;
    int tid = threadIdx.x;
    float x0 = a[tid];
    float x1 = a[tid+128];
    float x2 = a[tid+256];
    float m = fmaxf(x0, fmaxf(x1, x2));
    m = warpMax(m);
    if((tid&31)==0) sh[tid>>5]=m;
    __syncthreads();
    if(tid<32){ float mm=(tid<4)?sh[tid]:-1e30f; mm=warpMax(mm); if(tid==0) sh[0]=mm; }
    __syncthreads();
    m = sh[0];
    __syncthreads();
    x0 = __expf(x0-m); x1 = __expf(x1-m); x2 = __expf(x2-m);
    float s = warpRed(x0+x1+x2);
    if((tid&31)==0) sh[tid>>5]=s;
    __syncthreads();
    if(tid<32){ float ss=(tid<4)?sh[tid]:0.f; ss=warpRed(ss); if(tid==0) sh[0]=ss; }
    __syncthreads();
    s = sh[0];
    float rcp = __frcp_rn(s);
    __half* pp = p_pk + (size_t)row*384;
    pp[tid]     = __float2half(x0*rcp);
    pp[tid+128] = __float2half(x1*rcp);
    pp[tid+256] = __float2half(x2*rcp);
}

// ---------------- launch ----------------
extern "C" void kernel_launch(void* const* d_in, const int* in_sizes, int n_in,
                              void* d_out, int out_size){
    const float* msa       = (const float*)d_in[0];
    const float* pair      = (const float*)d_in[1];
    const float* ln_msa_g  = (const float*)d_in[2];
    const float* ln_msa_b  = (const float*)d_in[3];
    const float* ln_pair_g = (const float*)d_in[4];
    const float* ln_pair_b = (const float*)d_in[5];
    const float* sw_q_w    = (const float*)d_in[6];
    const float* sw_q_b    = (const float*)d_in[7];
    const float* sw_k_w    = (const float*)d_in[8];
    const float* sw_k_b    = (const float*)d_in[9];
    const float* wq        = (const float*)d_in[10];
    const float* wk        = (const float*)d_in[11];
    const float* wv        = (const float*)d_in[12];
    const float* wb        = (const float*)d_in[13];
    const float* wg        = (const float*)d_in[14];
    const float* bg        = (const float*)d_in[15];
    const float* wo        = (const float*)d_in[16];
    const float* bo        = (const float*)d_in[17];
    float* out = (float*)d_out;

    static cudaStream_t s2 = nullptr;
    static cudaEvent_t evFork = nullptr, evPack = nullptr, evBias = nullptr;
    if(s2 == nullptr){
        cudaStreamCreateWithFlags(&s2, cudaStreamNonBlocking);
        cudaEventCreateWithFlags(&evFork, cudaEventDisableTiming);
        cudaEventCreateWithFlags(&evPack, cudaEventDisableTiming);
        cudaEventCreateWithFlags(&evBias, cudaEventDisableTiming);
    }

    cudaFuncSetAttribute(gemm_mma<0>, cudaFuncAttributeMaxDynamicSharedMemorySize, GSMEM_BYTES);
    cudaFuncSetAttribute(gemm_mma<1>, cudaFuncAttributeMaxDynamicSharedMemorySize, GSMEM_BYTES);
    cudaFuncSetAttribute(gemm_mma<2>, cudaFuncAttributeMaxDynamicSharedMemorySize, GSMEM_BYTES);
    cudaFuncSetAttribute(gemm_mma<3>, cudaFuncAttributeMaxDynamicSharedMemorySize, GSMEM_BYTES);

    // fork side stream off the (possibly capturing) null stream
    cudaEventRecord(evFork, 0);
    cudaStreamWaitEvent(s2, evFork, 0);

    // side stream: pack weights, swq (self-contained LN), then pair bias
    pack_w_kernel<<<1536, 256, 0, s2>>>(wq, wk, wv, wg, sw_k_w, wo);
    swq_kernel<<<LR, 256, 0, s2>>>(msa, ln_msa_g, ln_msa_b, sw_q_w, sw_q_b, sw_k_b);
    cudaEventRecord(evPack, s2);
    bias_kernel<<<LL/8, 256, 0, s2>>>(pair, ln_pair_g, ln_pair_b, wb);   // seeds g_attn
    cudaEventRecord(evBias, s2);

    // main stream
    ln_msa_kernel<<<NL/8, 256>>>(msa, ln_msa_g, ln_msa_b);

    cudaStreamWaitEvent(0, evPack, 0);   // proj needs b_pk + g_swq/g_lbias
    // proj: [98304 x 1280], K=256
    gemm_mma<0><<<dim3(10, 768, 1), 128, GSMEM_BYTES>>>(bg, nullptr);

    seq_softmax_kernel<<<LR*NH, 256>>>();

    cudaStreamWaitEvent(0, evBias, 0);   // qk accumulates onto bias-seeded g_attn
    gemm_mma<1><<<dim3(3, 3, NH*4), 128, GSMEM_BYTES>>>(nullptr, nullptr);

    attn_softmax_kernel<<<NH*LR, 128>>>();

    gemm_mma<2><<<dim3(64, 3, NH), 128, GSMEM_BYTES>>>(nullptr, nullptr);

    gemm_mma<3><<<dim3(2, 768, 1), 128, GSMEM_BYTES>>>(bo, out);
}